// round 4
// baseline (speedup 1.0000x reference)
#include <cuda_runtime.h>
#include <cstdint>

// ============================================================================
// Problem constants (all static)
// ============================================================================
#define NMAX 8192
#define HDIM 128
#define KNN 5
#define CHUNKS 64

// ============================================================================
// Device scratch (no allocation allowed)
// ============================================================================
__device__ int   g_edges[2][NMAX * KNN];
__device__ float g_y[NMAX * HDIM];
__device__ float g_hA[NMAX * HDIM];   // GCN output (pre-pool)
__device__ float g_hB[NMAX * HDIM];   // pooled h (next stage input)
__device__ float g_xs[2][NMAX * HDIM];
__device__ int   g_perm[2][NMAX];
__device__ int   g_indeg[NMAX];
__device__ float g_dinv[NMAX];
__device__ float g_z[NMAX];
__device__ float g_score[NMAX];
__device__ unsigned long long g_keys[NMAX];
__device__ int   g_idx[NMAX];
__device__ float g_sv[NMAX];
__device__ int   g_newid[NMAX];
__device__ float g_racc[2 * HDIM];
__device__ int   g_hubs[8];
__device__ int   g_nhubs;
__device__ float g_part[CHUNKS * 5 * HDIM];

// ============================================================================
// Helpers
// ============================================================================
// Monotone float -> uint map (ascending)
__device__ __forceinline__ unsigned ordf(float v) {
    unsigned u = __float_as_uint(v);
    return (u & 0x80000000u) ? ~u : (u | 0x80000000u);
}

// ============================================================================
// Stage-0 degenerate edges (reference's eye*inf NaN semantics):
// knn[i] = [i, 4 lowest indices != i]  ->  off-diag out-edges:
//   i>=4 : {0,1,2,3} ; i<4 : {0..4}\{i}
// ============================================================================
__global__ void edges0_kernel(int* __restrict__ eout) {
    int i = blockIdx.x * 256 + threadIdx.x;
    if (i >= NMAX) return;
    int pos = 0;
    #pragma unroll
    for (int j = 0; j < 5; j++) {
        if (j != i && pos < 4) eout[i * 5 + (pos++)] = j;
    }
    eout[i * 5 + 4] = -1;
}

// ============================================================================
// Small utility kernels
// ============================================================================
__global__ void zero_f(float* p, int n) {
    int i = blockIdx.x * 256 + threadIdx.x;
    if (i < n) p[i] = 0.f;
}
__global__ void zero_i(int* p, int n) {
    int i = blockIdx.x * 256 + threadIdx.x;
    if (i < n) p[i] = 0;
}
__global__ void iota_kernel(int* p, int n) {
    int i = blockIdx.x * 256 + threadIdx.x;
    if (i < n) p[i] = i;
}

// in-degree count (excluding self-loop; deg = 1 + indeg)
__global__ void count_kernel(const int* __restrict__ edges, int* __restrict__ indeg, int n) {
    int r = blockIdx.x * 256 + threadIdx.x;
    if (r < n) {
        #pragma unroll
        for (int e = 0; e < 5; e++) {
            int c = edges[r * 5 + e];
            if (c >= 0) atomicAdd(&indeg[c], 1);
        }
    }
}

__global__ void dinv_kernel(const int* __restrict__ indeg, float* __restrict__ dinv, int n) {
    int i = blockIdx.x * 256 + threadIdx.x;
    if (i < n) {
        float deg = 1.f + (float)indeg[i];
        dinv[i] = 1.0f / sqrtf(deg);
    }
}

// collect hub columns (indeg > 0); structurally <= 5. Sorted ascending.
__global__ void hubs_kernel(const int* __restrict__ indeg, int n) {
    __shared__ int cnt;
    __shared__ int sl[8];
    int t = threadIdx.x;
    if (t == 0) cnt = 0;
    __syncthreads();
    for (int i = t; i < n; i += 1024) {
        if (indeg[i] > 0) {
            int p = atomicAdd(&cnt, 1);
            if (p < 8) sl[p] = i;
        }
    }
    __syncthreads();
    if (t == 0) {
        int m = cnt < 5 ? cnt : 5;
        // insertion sort ascending
        for (int i = 1; i < m; i++) {
            int v = sl[i], j = i - 1;
            while (j >= 0 && sl[j] > v) { sl[j + 1] = sl[j]; j--; }
            sl[j + 1] = v;
        }
        g_nhubs = m;
        #pragma unroll
        for (int k = 0; k < 5; k++) g_hubs[k] = (k < m) ? sl[k] : -1;
    }
}

// ============================================================================
// GEMM: y = h @ W  (16 rows per block, 128 threads = output cols, fp32)
// ============================================================================
__global__ void gemm16_kernel(const float* __restrict__ h, const float* __restrict__ W,
                              float* __restrict__ y) {
    __shared__ float hs[16][HDIM];
    int c = threadIdx.x;
    int r0 = blockIdx.x * 16;
    #pragma unroll
    for (int r = 0; r < 16; r++) hs[r][c] = h[(size_t)(r0 + r) * HDIM + c];
    __syncthreads();
    float acc[16];
    #pragma unroll
    for (int r = 0; r < 16; r++) acc[r] = 0.f;
    #pragma unroll 4
    for (int k = 0; k < HDIM; k++) {
        float w = W[k * HDIM + c];
        #pragma unroll
        for (int r = 0; r < 16; r++) acc[r] = fmaf(hs[r][k], w, acc[r]);
    }
    #pragma unroll
    for (int r = 0; r < 16; r++) y[(size_t)(r0 + r) * HDIM + c] = acc[r];
}

// ============================================================================
// GCN aggregation, exploiting diag + <=5 hub-column structure.
// base: out[c][f] = relu(dinv_c^2 * y[c][f] + b[f])   (exact for non-hubs)
// ============================================================================
__global__ void baseF_kernel(const float* __restrict__ y, const float* __restrict__ dinv,
                             const float* __restrict__ b, float* __restrict__ out, int n) {
    int idx = blockIdx.x * 256 + threadIdx.x;
    if (idx >= n * HDIM) return;
    int c = idx >> 7, f = idx & 127;
    float dc = dinv[c];
    float v = fmaf(dc * dc, y[idx], b[f]);
    out[idx] = fmaxf(v, 0.f);
}

// Phase A: per row-chunk partial sums of dinv_r*y_r into each hub (ascending r)
__global__ void hubpartF_kernel(const float* __restrict__ y, const float* __restrict__ dinv,
                                const int* __restrict__ edges, float* __restrict__ part,
                                int n) {
    __shared__ int hb[5];
    if (threadIdx.x < 5) hb[threadIdx.x] = g_hubs[threadIdx.x];
    __syncthreads();
    int f = threadIdx.x;
    int ch = blockIdx.x;
    int rpc = n >> 6;
    float acc[5] = {0.f, 0.f, 0.f, 0.f, 0.f};
    int rbeg = ch * rpc, rend = rbeg + rpc;
    for (int r = rbeg; r < rend; r++) {
        float wv = dinv[r] * y[(size_t)r * HDIM + f];
        int e0 = edges[r * 5 + 0], e1 = edges[r * 5 + 1], e2 = edges[r * 5 + 2];
        int e3 = edges[r * 5 + 3], e4 = edges[r * 5 + 4];
        #pragma unroll
        for (int k = 0; k < 5; k++) {
            int hv = hb[k];
            bool m = (hv >= 0) &&
                     (e0 == hv || e1 == hv || e2 == hv || e3 == hv || e4 == hv || r == hv);
            if (m) acc[k] += wv;
        }
    }
    #pragma unroll
    for (int k = 0; k < 5; k++) part[(ch * 5 + k) * HDIM + f] = acc[k];
}

// Phase B: reduce chunks (ascending), write hub rows
__global__ void hubfixF_kernel(const float* __restrict__ part, const float* __restrict__ dinv,
                               const float* __restrict__ b, float* __restrict__ out) {
    int k = blockIdx.x;
    if (k >= g_nhubs) return;
    int f = threadIdx.x;
    float S = 0.f;
    for (int ch = 0; ch < CHUNKS; ch++) S += part[(ch * 5 + k) * HDIM + f];
    int c = g_hubs[k];
    float v = fmaf(dinv[c], S, b[f]);
    out[(size_t)c * HDIM + f] = fmaxf(v, 0.f);
}

// ============================================================================
// Score GCN: z = h . Wp, then same diag+hub aggregation (scalar)
// ============================================================================
__global__ void zdot_kernel(const float* __restrict__ h, const float* __restrict__ Wp,
                            float* __restrict__ z, int n) {
    int w = threadIdx.x >> 5, lane = threadIdx.x & 31;
    int r = blockIdx.x * 8 + w;
    if (r >= n) return;
    float s = 0.f;
    #pragma unroll
    for (int kk = lane; kk < HDIM; kk += 32)
        s = fmaf(h[(size_t)r * HDIM + kk], Wp[kk], s);
    #pragma unroll
    for (int o = 16; o > 0; o >>= 1) s += __shfl_down_sync(0xffffffffu, s, o);
    if (lane == 0) z[r] = s;
}

__global__ void baseS_kernel(const float* __restrict__ z, const float* __restrict__ dinv,
                             const float* __restrict__ bp, float* __restrict__ score, int n) {
    int c = blockIdx.x * 256 + threadIdx.x;
    if (c >= n) return;
    float dc = dinv[c];
    score[c] = fmaf(dc * dc, z[c], bp[0]);
}

__global__ void hubfixS_kernel(const float* __restrict__ z, const float* __restrict__ dinv,
                               const int* __restrict__ edges, const float* __restrict__ bp,
                               float* __restrict__ score, int n) {
    int k = blockIdx.x;
    if (k >= g_nhubs) return;
    int hub = g_hubs[k];
    __shared__ float red[256];
    int t = threadIdx.x;
    float p = 0.f;
    for (int r = t; r < n; r += 256) {
        int e0 = edges[r * 5 + 0], e1 = edges[r * 5 + 1], e2 = edges[r * 5 + 2];
        int e3 = edges[r * 5 + 3], e4 = edges[r * 5 + 4];
        bool m = (e0 == hub || e1 == hub || e2 == hub || e3 == hub || e4 == hub || r == hub);
        if (m) p += dinv[r] * z[r];
    }
    red[t] = p;
    __syncthreads();
    for (int o = 128; o > 0; o >>= 1) {
        if (t < o) red[t] += red[t + o];
        __syncthreads();
    }
    if (t == 0) score[hub] = fmaf(dinv[hub], red[0], bp[0]);
}

// ============================================================================
// Top-k machinery (jax-stable: desc value, asc index on ties)
// ============================================================================
__global__ void keys_kernel(const float* __restrict__ score,
                            unsigned long long* __restrict__ keys, int n) {
    int i = blockIdx.x * 256 + threadIdx.x;
    if (i < n)
        keys[i] = ((unsigned long long)(~ordf(score[i])) << 32) | (unsigned)i;
}

__global__ void bitonic_kernel(unsigned long long* __restrict__ keys, int n) {
    extern __shared__ unsigned long long sk[];
    int t = threadIdx.x;
    for (int i = t; i < n; i += 1024) sk[i] = keys[i];
    __syncthreads();
    for (int k = 2; k <= n; k <<= 1) {
        for (int j = k >> 1; j > 0; j >>= 1) {
            for (int i = t; i < n; i += 1024) {
                int ixj = i ^ j;
                if (ixj > i) {
                    unsigned long long a = sk[i], b = sk[ixj];
                    bool up = ((i & k) == 0);
                    if ((a > b) == up) { sk[i] = b; sk[ixj] = a; }
                }
            }
            __syncthreads();
        }
    }
    for (int i = t; i < n; i += 1024) keys[i] = sk[i];
}

__global__ void extract_kernel(const unsigned long long* __restrict__ keys,
                               const float* __restrict__ score,
                               int* __restrict__ idx, float* __restrict__ sv, int k) {
    int a = blockIdx.x * 256 + threadIdx.x;
    if (a < k) {
        int id = (int)(keys[a] & 0xffffffffull);
        idx[a] = id;
        sv[a] = score[id];
    }
}

__global__ void nidinit_kernel(int* __restrict__ newid, int n) {
    int i = blockIdx.x * 256 + threadIdx.x;
    if (i < n) newid[i] = -1;
}
__global__ void nidset_kernel(const int* __restrict__ idx, int* __restrict__ newid, int k) {
    int a = blockIdx.x * 256 + threadIdx.x;
    if (a < k) newid[idx[a]] = a;
}

// gather + gate + remap edges
__global__ void pool_kernel(const float* __restrict__ h, const float* __restrict__ xs,
                            const int* __restrict__ perm, const int* __restrict__ edges,
                            const int* __restrict__ idx, const float* __restrict__ sv,
                            const int* __restrict__ newid,
                            float* __restrict__ h2, float* __restrict__ xs2,
                            int* __restrict__ perm2, int* __restrict__ edges2) {
    int a = blockIdx.x, t = threadIdx.x;
    int o = idx[a];
    float g = tanhf(sv[a]);
    h2[(size_t)a * HDIM + t] = h[(size_t)o * HDIM + t] * g;
    xs2[(size_t)a * HDIM + t] = xs[(size_t)o * HDIM + t];
    if (t == 0) perm2[a] = perm[o];
    if (t < 5) {
        int e = edges[o * 5 + t];
        int ne = (e >= 0) ? newid[e] : -1;
        edges2[a * 5 + t] = ne;
    }
}

// per-feature max & mean over k rows, accumulated across stages
__global__ void readout_kernel(const float* __restrict__ h, float* __restrict__ racc, int k) {
    int f = blockIdx.x, t = threadIdx.x;
    __shared__ float smx[256], ssm[256];
    float mx = -3.4e38f, s = 0.f;
    for (int r = t; r < k; r += 256) {
        float v = h[(size_t)r * HDIM + f];
        mx = fmaxf(mx, v);
        s += v;
    }
    smx[t] = mx;
    ssm[t] = s;
    __syncthreads();
    for (int o = 128; o > 0; o >>= 1) {
        if (t < o) {
            smx[t] = fmaxf(smx[t], smx[t + o]);
            ssm[t] += ssm[t + o];
        }
        __syncthreads();
    }
    if (t == 0) {
        racc[f] += smx[0];
        racc[HDIM + f] += ssm[0] / (float)k;
    }
}

// final MLP + log_softmax -> out[0..40)
__global__ void mlp_kernel(const float* __restrict__ racc,
                           const float* __restrict__ L1w, const float* __restrict__ L1b,
                           const float* __restrict__ L2w, const float* __restrict__ L2b,
                           const float* __restrict__ L3w, const float* __restrict__ L3b,
                           float* __restrict__ out) {
    __shared__ float z[256], z1[128], z2[64], z3[40];
    int t = threadIdx.x;
    z[t] = racc[t];
    __syncthreads();
    if (t < 128) {
        float a = 0.f;
        for (int i = 0; i < 256; i++) a = fmaf(z[i], L1w[i * 128 + t], a);
        z1[t] = fmaxf(a + L1b[t], 0.f);
    }
    __syncthreads();
    if (t < 64) {
        float a = 0.f;
        for (int i = 0; i < 128; i++) a = fmaf(z1[i], L2w[i * 64 + t], a);
        z2[t] = fmaxf(a + L2b[t], 0.f);
    }
    __syncthreads();
    if (t < 40) {
        float a = 0.f;
        for (int i = 0; i < 64; i++) a = fmaf(z2[i], L3w[i * 40 + t], a);
        z3[t] = a + L3b[t];
    }
    __syncthreads();
    if (t == 0) {
        float m = z3[0];
        for (int i = 1; i < 40; i++) m = fmaxf(m, z3[i]);
        float s = 0.f;
        for (int i = 0; i < 40; i++) s += expf(z3[i] - m);
        float l = m + logf(s);
        for (int i = 0; i < 40; i++) out[i] = z3[i] - l;
    }
}

// write xs [1024,128] and perm [1024] (as float)
__global__ void outxp_kernel(const float* __restrict__ xs, const int* __restrict__ perm,
                             float* __restrict__ out) {
    int i = blockIdx.x * 256 + threadIdx.x;
    if (i < 1024 * HDIM) out[40 + i] = xs[i];
    else if (i < 1024 * HDIM + 1024) out[40 + 1024 * HDIM + (i - 1024 * HDIM)] =
        (float)perm[i - 1024 * HDIM];
}

// densify A3 [1024,1024]
__global__ void a3_kernel(const int* __restrict__ edges, float* __restrict__ out) {
    int b = blockIdx.x;
    float* row = out + (size_t)b * 1024;
    for (int i = threadIdx.x; i < 1024; i += 256) row[i] = 0.f;
    __syncthreads();
    if (threadIdx.x == 0) {
        row[b] = 1.f;
        #pragma unroll
        for (int e = 0; e < 5; e++) {
            int tgt = edges[b * 5 + e];
            if (tgt >= 0) row[tgt] = 1.f;
        }
    }
}

// ============================================================================
// Host launcher
// ============================================================================
extern "C" void kernel_launch(void* const* d_in, const int* in_sizes, int n_in,
                              void* d_out, int out_size) {
    (void)in_sizes; (void)n_in; (void)out_size;
    const float* W[3]  = {(const float*)d_in[2], (const float*)d_in[4], (const float*)d_in[6]};
    const float* bb[3] = {(const float*)d_in[3], (const float*)d_in[5], (const float*)d_in[7]};
    const float* Wp[3] = {(const float*)d_in[8], (const float*)d_in[10], (const float*)d_in[12]};
    const float* bp[3] = {(const float*)d_in[9], (const float*)d_in[11], (const float*)d_in[13]};
    const float* x0  = (const float*)d_in[0];
    const float* L1w = (const float*)d_in[14];
    const float* L1b = (const float*)d_in[15];
    const float* L2w = (const float*)d_in[16];
    const float* L2b = (const float*)d_in[17];
    const float* L3w = (const float*)d_in[18];
    const float* L3b = (const float*)d_in[19];
    float* out = (float*)d_out;

    float *p_y, *p_hA, *p_hB, *p_dinv, *p_z, *p_score, *p_sv, *p_racc, *p_xsb, *p_part;
    int *p_edgesb, *p_indeg, *p_idx, *p_newid, *p_permb;
    unsigned long long* p_keys;
    cudaGetSymbolAddress((void**)&p_edgesb, g_edges);
    cudaGetSymbolAddress((void**)&p_y, g_y);
    cudaGetSymbolAddress((void**)&p_hA, g_hA);
    cudaGetSymbolAddress((void**)&p_hB, g_hB);
    cudaGetSymbolAddress((void**)&p_xsb, g_xs);
    cudaGetSymbolAddress((void**)&p_permb, g_perm);
    cudaGetSymbolAddress((void**)&p_indeg, g_indeg);
    cudaGetSymbolAddress((void**)&p_dinv, g_dinv);
    cudaGetSymbolAddress((void**)&p_z, g_z);
    cudaGetSymbolAddress((void**)&p_score, g_score);
    cudaGetSymbolAddress((void**)&p_keys, g_keys);
    cudaGetSymbolAddress((void**)&p_idx, g_idx);
    cudaGetSymbolAddress((void**)&p_sv, g_sv);
    cudaGetSymbolAddress((void**)&p_newid, g_newid);
    cudaGetSymbolAddress((void**)&p_racc, g_racc);
    cudaGetSymbolAddress((void**)&p_part, g_part);

    int* p_edges[2] = {p_edgesb, p_edgesb + NMAX * KNN};
    float* p_xs[2] = {p_xsb, p_xsb + (size_t)NMAX * HDIM};
    int* p_perm[2] = {p_permb, p_permb + NMAX};

    cudaFuncSetAttribute(bitonic_kernel,
                         cudaFuncAttributeMaxDynamicSharedMemorySize, 65536);

    // --- degenerate graph build (reference's eye*inf NaN semantics) ---
    edges0_kernel<<<NMAX / 256, 256>>>(p_edges[0]);

    // --- init accumulators / identity perm ---
    zero_f<<<1, 256>>>(p_racc, 256);
    iota_kernel<<<NMAX / 256, 256>>>(p_perm[1], NMAX);

    // --- 3 stages ---
    for (int s = 0; s < 3; s++) {
        int n = NMAX >> s;
        int k = n >> 1;
        int nb = (n + 255) / 256;
        int* ecur = p_edges[s & 1];
        int* enext = p_edges[(s + 1) & 1];

        // degrees, dinv, hub set
        zero_i<<<nb, 256>>>(p_indeg, n);
        count_kernel<<<nb, 256>>>(ecur, p_indeg, n);
        dinv_kernel<<<nb, 256>>>(p_indeg, p_dinv, n);
        hubs_kernel<<<1, 1024>>>(p_indeg, n);

        // GCN feature layer
        const float* hin = (s == 0) ? x0 : p_hB;
        gemm16_kernel<<<n / 16, 128>>>(hin, W[s], p_y);
        baseF_kernel<<<(n * HDIM + 255) / 256, 256>>>(p_y, p_dinv, bb[s], p_hA, n);
        hubpartF_kernel<<<CHUNKS, 128>>>(p_y, p_dinv, ecur, p_part, n);
        hubfixF_kernel<<<5, 128>>>(p_part, p_dinv, bb[s], p_hA);

        // pooling score GCN
        zdot_kernel<<<(n + 7) / 8, 256>>>(p_hA, Wp[s], p_z, n);
        baseS_kernel<<<nb, 256>>>(p_z, p_dinv, bp[s], p_score, n);
        hubfixS_kernel<<<5, 256>>>(p_z, p_dinv, ecur, bp[s], p_score, n);

        // top-k (full bitonic sort, jax-stable tie-break)
        keys_kernel<<<nb, 256>>>(p_score, p_keys, n);
        bitonic_kernel<<<1, 1024, n * 8>>>(p_keys, n);
        extract_kernel<<<(k + 255) / 256, 256>>>(p_keys, p_score, p_idx, p_sv, k);
        nidinit_kernel<<<nb, 256>>>(p_newid, n);
        nidset_kernel<<<(k + 255) / 256, 256>>>(p_idx, p_newid, k);

        // pool: gather h/xs/perm, remap edges
        const float* xin = (s == 0) ? x0 : p_xs[(s - 1) & 1];
        const int* pin = (s == 0) ? p_perm[1] : p_perm[(s - 1) & 1];
        pool_kernel<<<k, 128>>>(p_hA, xin, pin, ecur, p_idx, p_sv, p_newid,
                                p_hB, p_xs[s & 1], p_perm[s & 1], enext);

        // readout accumulate
        readout_kernel<<<HDIM, 256>>>(p_hB, p_racc, k);
    }

    // --- head + outputs ---
    mlp_kernel<<<1, 256>>>(p_racc, L1w, L1b, L2w, L2b, L3w, L3b, out);
    outxp_kernel<<<(1024 * HDIM + 1024 + 255) / 256, 256>>>(p_xs[0], p_perm[0], out);
    a3_kernel<<<1024, 256>>>(p_edges[1], out + 40 + 1024 * HDIM + 1024);
}

// round 6
// speedup vs baseline: 1.2774x; 1.2774x over previous
#include <cuda_runtime.h>
#include <cstdint>

#define NMAX 8192
#define HDIM 128
#define RPB 32      // rows per gemm block
#define CHUNK 2048  // sort chunk per block
#define CHUNKS 64   // hub-partial chunks (R4-exact)

// ============================================================================
// Device scratch
// ============================================================================
__device__ int   g_edges[2][NMAX * 5];
__device__ float g_y[NMAX * HDIM];
__device__ float g_hA[NMAX * HDIM];
__device__ float g_hB[NMAX * HDIM];
__device__ float g_xs[2][NMAX * HDIM];
__device__ int   g_perm[2][NMAX];
__device__ int   g_indeg[NMAX];
__device__ float g_dinv[NMAX];
__device__ float g_z[NMAX];
__device__ float g_score[NMAX];
__device__ unsigned long long g_keys[NMAX];
__device__ int   g_idx[NMAX];
__device__ float g_sv[NMAX];
__device__ int   g_newid[NMAX];
__device__ int   g_hubs[5];
__device__ int   g_nhubs;
__device__ float g_part[CHUNKS * 5 * HDIM];
__device__ unsigned g_rmax[3][HDIM];
__device__ float g_rsum[3][HDIM];

// ============================================================================
// Helpers
// ============================================================================
__device__ __forceinline__ unsigned ordf(float v) {
    unsigned u = __float_as_uint(v);
    return (u & 0x80000000u) ? ~u : (u | 0x80000000u);
}
__device__ __forceinline__ float deco(unsigned e) {
    unsigned u = (e & 0x80000000u) ? (e & 0x7fffffffu) : ~e;
    return __uint_as_float(u);
}

// ============================================================================
// Init: degenerate stage-0 edges (eye*inf NaN semantics), closed-form indeg,
// zero readout accumulators.
// ============================================================================
__global__ void init_kernel(int* __restrict__ eout, int* __restrict__ indeg) {
    int i = blockIdx.x * 256 + threadIdx.x;
    if (i < NMAX) {
        int pos = 0;
        #pragma unroll
        for (int j = 0; j < 5; j++)
            if (j != i && pos < 4) eout[i * 5 + (pos++)] = j;
        eout[i * 5 + 4] = -1;
        indeg[i] = (i < 4) ? (NMAX - 1) : ((i == 4) ? 4 : 0);
    }
    if (i < 3 * HDIM) {
        (&g_rmax[0][0])[i] = 0u;
        (&g_rsum[0][0])[i] = 0.f;
    }
}

// ============================================================================
// dinv + hub detection (1 block) — dinv expression identical to R4
// ============================================================================
__global__ void dinvhubs_kernel(const int* __restrict__ indeg,
                                float* __restrict__ dinv, int n) {
    __shared__ int cnt;
    __shared__ int sl[16];
    int t = threadIdx.x;
    if (t == 0) cnt = 0;
    __syncthreads();
    for (int i = t; i < n; i += 1024) {
        int d = indeg[i];
        float deg = 1.f + (float)d;
        dinv[i] = 1.0f / sqrtf(deg);
        if (d > 0) {
            int p = atomicAdd(&cnt, 1);
            if (p < 16) sl[p] = i;
        }
    }
    __syncthreads();
    if (t == 0) {
        int m = cnt < 5 ? cnt : 5;
        for (int i = 1; i < m; i++) {
            int v = sl[i], j = i - 1;
            while (j >= 0 && sl[j] > v) { sl[j + 1] = sl[j]; j--; }
            sl[j + 1] = v;
        }
        g_nhubs = m;
        #pragma unroll
        for (int k = 0; k < 5; k++) g_hubs[k] = (k < m) ? sl[k] : -1;
    }
}

// ============================================================================
// Fused GEMM + base hA: y = h@W (32 rows/block, ascending-k fmaf chain ==
// R4 bits), y stored for hub pipeline, hA = relu(dinv^2*y + b) (R4 bits).
// ============================================================================
__global__ void gemmF_kernel(const float* __restrict__ h, const float* __restrict__ W,
                             const float* __restrict__ b, const float* __restrict__ dinv,
                             float* __restrict__ y, float* __restrict__ hA) {
    __shared__ float hs[RPB][HDIM];
    __shared__ float sdi[RPB];
    const int c = threadIdx.x;
    const int r0 = blockIdx.x * RPB;
    if (c < RPB) sdi[c] = dinv[r0 + c];
    #pragma unroll
    for (int r = 0; r < RPB; r++) hs[r][c] = h[(size_t)(r0 + r) * HDIM + c];
    __syncthreads();
    float acc[RPB];
    #pragma unroll
    for (int r = 0; r < RPB; r++) acc[r] = 0.f;
    #pragma unroll 4
    for (int k = 0; k < HDIM; k++) {
        float w = W[k * HDIM + c];
        #pragma unroll
        for (int r = 0; r < RPB; r++) acc[r] = fmaf(hs[r][k], w, acc[r]);
    }
    float bc = b[c];
    #pragma unroll
    for (int r = 0; r < RPB; r++) {
        y[(size_t)(r0 + r) * HDIM + c] = acc[r];
        float dc = sdi[r];
        float v = fmaf(dc * dc, acc[r], bc);
        hA[(size_t)(r0 + r) * HDIM + c] = fmaxf(v, 0.f);
    }
}

// ============================================================================
// R4-verbatim hub partials: 64 chunks, ascending rows, fadd chain
// ============================================================================
__global__ void hubpartF_kernel(const float* __restrict__ y, const float* __restrict__ dinv,
                                const int* __restrict__ edges, float* __restrict__ part,
                                int n) {
    __shared__ int hb[5];
    if (threadIdx.x < 5) hb[threadIdx.x] = g_hubs[threadIdx.x];
    __syncthreads();
    int f = threadIdx.x;
    int ch = blockIdx.x;
    int rpc = n >> 6;
    float acc[5] = {0.f, 0.f, 0.f, 0.f, 0.f};
    int rbeg = ch * rpc, rend = rbeg + rpc;
    for (int r = rbeg; r < rend; r++) {
        float wv = dinv[r] * y[(size_t)r * HDIM + f];
        int e0 = edges[r * 5 + 0], e1 = edges[r * 5 + 1], e2 = edges[r * 5 + 2];
        int e3 = edges[r * 5 + 3], e4 = edges[r * 5 + 4];
        #pragma unroll
        for (int k = 0; k < 5; k++) {
            int hv = hb[k];
            bool m = (hv >= 0) &&
                     (e0 == hv || e1 == hv || e2 == hv || e3 == hv || e4 == hv || r == hv);
            if (m) acc[k] += wv;
        }
    }
    #pragma unroll
    for (int k = 0; k < 5; k++) part[(ch * 5 + k) * HDIM + f] = acc[k];
}

// R4-verbatim: reduce chunks ascending, write hub hA rows
__global__ void hubfixF_kernel(const float* __restrict__ part, const float* __restrict__ dinv,
                               const float* __restrict__ b, float* __restrict__ out) {
    int k = blockIdx.x;
    if (k >= g_nhubs) return;
    int f = threadIdx.x;
    float S = 0.f;
    for (int ch = 0; ch < CHUNKS; ch++) S += part[(ch * 5 + k) * HDIM + f];
    int c = g_hubs[k];
    float v = fmaf(dinv[c], S, b[f]);
    out[(size_t)c * HDIM + f] = fmaxf(v, 0.f);
}

// ============================================================================
// R4-verbatim z: warp per row, strided fmaf chain, shfl tree
// ============================================================================
__global__ void zdot_kernel(const float* __restrict__ h, const float* __restrict__ Wp,
                            float* __restrict__ z, int n) {
    int w = threadIdx.x >> 5, lane = threadIdx.x & 31;
    int r = blockIdx.x * 8 + w;
    if (r >= n) return;
    float s = 0.f;
    #pragma unroll
    for (int kk = lane; kk < HDIM; kk += 32)
        s = fmaf(h[(size_t)r * HDIM + kk], Wp[kk], s);
    #pragma unroll
    for (int o = 16; o > 0; o >>= 1) s += __shfl_down_sync(0xffffffffu, s, o);
    if (lane == 0) z[r] = s;
}

// R4-verbatim base score (+ fused key pack of identical score bits)
__global__ void baseSK_kernel(const float* __restrict__ z, const float* __restrict__ dinv,
                              const float* __restrict__ bp, float* __restrict__ score,
                              unsigned long long* __restrict__ keys, int n) {
    int c = blockIdx.x * 256 + threadIdx.x;
    if (c >= n) return;
    float dc = dinv[c];
    float sc = fmaf(dc * dc, z[c], bp[0]);
    score[c] = sc;
    keys[c] = ((unsigned long long)(~ordf(sc)) << 32) | (unsigned)c;
}

// R4-verbatim hub score (256 threads, strided, tree) + fused key pack
__global__ void hubfixSK_kernel(const float* __restrict__ z, const float* __restrict__ dinv,
                                const int* __restrict__ edges, const float* __restrict__ bp,
                                float* __restrict__ score,
                                unsigned long long* __restrict__ keys, int n) {
    int k = blockIdx.x;
    if (k >= g_nhubs) return;
    int hub = g_hubs[k];
    __shared__ float red[256];
    int t = threadIdx.x;
    float p = 0.f;
    for (int r = t; r < n; r += 256) {
        int e0 = edges[r * 5 + 0], e1 = edges[r * 5 + 1], e2 = edges[r * 5 + 2];
        int e3 = edges[r * 5 + 3], e4 = edges[r * 5 + 4];
        bool m = (e0 == hub || e1 == hub || e2 == hub || e3 == hub || e4 == hub || r == hub);
        if (m) p += dinv[r] * z[r];
    }
    red[t] = p;
    __syncthreads();
    for (int o = 128; o > 0; o >>= 1) {
        if (t < o) red[t] += red[t + o];
        __syncthreads();
    }
    if (t == 0) {
        float sc = fmaf(dinv[hub], red[0], bp[0]);
        score[hub] = sc;
        keys[hub] = ((unsigned long long)(~ordf(sc)) << 32) | (unsigned)hub;
    }
}

// ============================================================================
// Multi-block bitonic sort
// ============================================================================
__global__ void sort_local_kernel(unsigned long long* __restrict__ keys) {
    __shared__ unsigned long long sk[CHUNK];
    int t = threadIdx.x;
    int g0 = blockIdx.x * CHUNK;
    sk[t] = keys[g0 + t];
    sk[t + 1024] = keys[g0 + t + 1024];
    __syncthreads();
    for (int k = 2; k <= CHUNK; k <<= 1) {
        for (int j = k >> 1; j > 0; j >>= 1) {
            int i = ((t / j) * 2 * j) + (t % j);
            int ixj = i + j;
            bool up = (((g0 + i) & k) == 0);
            unsigned long long a = sk[i], bb = sk[ixj];
            if ((a > bb) == up) { sk[i] = bb; sk[ixj] = a; }
            __syncthreads();
        }
    }
    keys[g0 + t] = sk[t];
    keys[g0 + t + 1024] = sk[t + 1024];
}

__global__ void sort_cross_kernel(unsigned long long* __restrict__ keys,
                                  int n, int k, int j) {
    int t = blockIdx.x * 256 + threadIdx.x;
    if (t >= n / 2) return;
    int i = ((t / j) * 2 * j) + (t % j);
    int ixj = i + j;
    bool up = ((i & k) == 0);
    unsigned long long a = keys[i], bb = keys[ixj];
    if ((a > bb) == up) { keys[i] = bb; keys[ixj] = a; }
}

__global__ void sort_finish_kernel(unsigned long long* __restrict__ keys, int k) {
    __shared__ unsigned long long sk[CHUNK];
    int t = threadIdx.x;
    int g0 = blockIdx.x * CHUNK;
    sk[t] = keys[g0 + t];
    sk[t + 1024] = keys[g0 + t + 1024];
    __syncthreads();
    for (int j = 1024; j > 0; j >>= 1) {
        int i = ((t / j) * 2 * j) + (t % j);
        int ixj = i + j;
        bool up = (((g0 + i) & k) == 0);
        unsigned long long a = sk[i], bb = sk[ixj];
        if ((a > bb) == up) { sk[i] = bb; sk[ixj] = a; }
        __syncthreads();
    }
    keys[g0 + t] = sk[t];
    keys[g0 + t + 1024] = sk[t + 1024];
}

// ============================================================================
// Extract + newid + zero next indeg (keys form a permutation of node ids)
// ============================================================================
__global__ void extract_kernel(const unsigned long long* __restrict__ keys,
                               const float* __restrict__ score,
                               int* __restrict__ idx, float* __restrict__ sv,
                               int* __restrict__ newid, int* __restrict__ indeg,
                               int n, int k) {
    int i = blockIdx.x * 256 + threadIdx.x;
    if (i >= n) return;
    int id = (int)(keys[i] & 0xffffffffull);
    newid[id] = (i < k) ? i : -1;
    if (i < k) {
        idx[i] = id;
        sv[i] = score[id];
        indeg[i] = 0;
    }
}

// ============================================================================
// Pool (32 new nodes/block): gather+gate h, gather xs/perm, remap edges,
// next indeg count, block-reduced readout atomics (set-invariant).
// ============================================================================
__global__ void pool_kernel(const float* __restrict__ h, const float* __restrict__ xs,
                            const int* __restrict__ perm, const int* __restrict__ edges,
                            const int* __restrict__ idx, const float* __restrict__ sv,
                            const int* __restrict__ newid,
                            float* __restrict__ h2, float* __restrict__ xs2,
                            int* __restrict__ perm2, int* __restrict__ edges2,
                            int* __restrict__ indeg, int stage) {
    __shared__ int sidx[32];
    __shared__ float sg[32];
    int c = threadIdx.x;
    int a0 = blockIdx.x * 32;
    if (c < 32) {
        sidx[c] = idx[a0 + c];
        sg[c] = tanhf(sv[a0 + c]);
    }
    __syncthreads();
    float lmax = -3.4e38f, lsum = 0.f;
    for (int rr = 0; rr < 32; rr++) {
        int a = a0 + rr;
        int o = sidx[rr];
        float v = h[(size_t)o * HDIM + c] * sg[rr];
        h2[(size_t)a * HDIM + c] = v;
        xs2[(size_t)a * HDIM + c] = xs[(size_t)o * HDIM + c];
        lmax = fmaxf(lmax, v);
        lsum += v;
        if (c < 5) {
            int e = edges[o * 5 + c];
            int ne = (e >= 0) ? newid[e] : -1;
            edges2[a * 5 + c] = ne;
            if (ne >= 0) atomicAdd(&indeg[ne], 1);
        }
        if (c == 5) perm2[a] = (perm != nullptr) ? perm[o] : o;
    }
    atomicMax(&g_rmax[stage][c], ordf(lmax));
    atomicAdd(&g_rsum[stage][c], lsum);
}

// ============================================================================
// Final MLP + log_softmax
// ============================================================================
__global__ void mlp_kernel(const float* __restrict__ L1w, const float* __restrict__ L1b,
                           const float* __restrict__ L2w, const float* __restrict__ L2b,
                           const float* __restrict__ L3w, const float* __restrict__ L3b,
                           float* __restrict__ out) {
    __shared__ float zin[256], z1[128], z2[64], z3[40];
    int t = threadIdx.x;
    if (t < 128) {
        zin[t] = deco(g_rmax[0][t]) + deco(g_rmax[1][t]) + deco(g_rmax[2][t]);
        zin[128 + t] = g_rsum[0][t] / 4096.f + g_rsum[1][t] / 2048.f + g_rsum[2][t] / 1024.f;
    }
    __syncthreads();
    if (t < 128) {
        float a = 0.f;
        for (int i = 0; i < 256; i++) a = fmaf(zin[i], L1w[i * 128 + t], a);
        z1[t] = fmaxf(a + L1b[t], 0.f);
    }
    __syncthreads();
    if (t < 64) {
        float a = 0.f;
        for (int i = 0; i < 128; i++) a = fmaf(z1[i], L2w[i * 64 + t], a);
        z2[t] = fmaxf(a + L2b[t], 0.f);
    }
    __syncthreads();
    if (t < 40) {
        float a = 0.f;
        for (int i = 0; i < 64; i++) a = fmaf(z2[i], L3w[i * 40 + t], a);
        z3[t] = a + L3b[t];
    }
    __syncthreads();
    if (t == 0) {
        float m = z3[0];
        for (int i = 1; i < 40; i++) m = fmaxf(m, z3[i]);
        float s = 0.f;
        for (int i = 0; i < 40; i++) s += expf(z3[i] - m);
        float l = m + logf(s);
        for (int i = 0; i < 40; i++) out[i] = z3[i] - l;
    }
}

__global__ void outxp_kernel(const float* __restrict__ xs, const int* __restrict__ perm,
                             float* __restrict__ out) {
    int i = blockIdx.x * 256 + threadIdx.x;
    if (i < 1024 * HDIM) out[40 + i] = xs[i];
    else if (i < 1024 * HDIM + 1024)
        out[40 + 1024 * HDIM + (i - 1024 * HDIM)] = (float)perm[i - 1024 * HDIM];
}

__global__ void a3_kernel(const int* __restrict__ edges, float* __restrict__ out) {
    int b = blockIdx.x;
    float* row = out + (size_t)b * 1024;
    for (int i = threadIdx.x; i < 1024; i += 256) row[i] = 0.f;
    __syncthreads();
    if (threadIdx.x == 0) {
        row[b] = 1.f;
        #pragma unroll
        for (int e = 0; e < 5; e++) {
            int tgt = edges[b * 5 + e];
            if (tgt >= 0) row[tgt] = 1.f;
        }
    }
}

// ============================================================================
// Host launcher
// ============================================================================
extern "C" void kernel_launch(void* const* d_in, const int* in_sizes, int n_in,
                              void* d_out, int out_size) {
    (void)in_sizes; (void)n_in; (void)out_size;
    const float* x0  = (const float*)d_in[0];
    const float* W[3]  = {(const float*)d_in[2], (const float*)d_in[4], (const float*)d_in[6]};
    const float* bb[3] = {(const float*)d_in[3], (const float*)d_in[5], (const float*)d_in[7]};
    const float* Wp[3] = {(const float*)d_in[8], (const float*)d_in[10], (const float*)d_in[12]};
    const float* bp[3] = {(const float*)d_in[9], (const float*)d_in[11], (const float*)d_in[13]};
    const float* L1w = (const float*)d_in[14];
    const float* L1b = (const float*)d_in[15];
    const float* L2w = (const float*)d_in[16];
    const float* L2b = (const float*)d_in[17];
    const float* L3w = (const float*)d_in[18];
    const float* L3b = (const float*)d_in[19];
    float* out = (float*)d_out;

    float *p_y, *p_hA, *p_hB, *p_dinv, *p_z, *p_score, *p_sv, *p_xsb, *p_part;
    int *p_edgesb, *p_indeg, *p_idx, *p_newid, *p_permb;
    unsigned long long* p_keys;
    cudaGetSymbolAddress((void**)&p_edgesb, g_edges);
    cudaGetSymbolAddress((void**)&p_y, g_y);
    cudaGetSymbolAddress((void**)&p_hA, g_hA);
    cudaGetSymbolAddress((void**)&p_hB, g_hB);
    cudaGetSymbolAddress((void**)&p_xsb, g_xs);
    cudaGetSymbolAddress((void**)&p_permb, g_perm);
    cudaGetSymbolAddress((void**)&p_indeg, g_indeg);
    cudaGetSymbolAddress((void**)&p_dinv, g_dinv);
    cudaGetSymbolAddress((void**)&p_z, g_z);
    cudaGetSymbolAddress((void**)&p_score, g_score);
    cudaGetSymbolAddress((void**)&p_keys, g_keys);
    cudaGetSymbolAddress((void**)&p_idx, g_idx);
    cudaGetSymbolAddress((void**)&p_sv, g_sv);
    cudaGetSymbolAddress((void**)&p_newid, g_newid);
    cudaGetSymbolAddress((void**)&p_part, g_part);

    int* p_edges[2] = {p_edgesb, p_edgesb + NMAX * 5};
    float* p_xs[2] = {p_xsb, p_xsb + (size_t)NMAX * HDIM};
    int* p_perm[2] = {p_permb, p_permb + NMAX};

    init_kernel<<<NMAX / 256, 256>>>(p_edges[0], p_indeg);

    for (int s = 0; s < 3; s++) {
        int n = NMAX >> s;
        int k = n >> 1;
        int nb = (n + 255) / 256;
        int* ecur = p_edges[s & 1];
        int* enext = p_edges[(s + 1) & 1];
        const float* hin = (s == 0) ? x0 : p_hB;
        const float* xin = (s == 0) ? x0 : p_xs[(s - 1) & 1];
        const int* pin = (s == 0) ? nullptr : p_perm[(s - 1) & 1];

        dinvhubs_kernel<<<1, 1024>>>(p_indeg, p_dinv, n);

        // feature pipeline (score bits == R4)
        gemmF_kernel<<<n / RPB, 128>>>(hin, W[s], bb[s], p_dinv, p_y, p_hA);
        hubpartF_kernel<<<CHUNKS, 128>>>(p_y, p_dinv, ecur, p_part, n);
        hubfixF_kernel<<<5, 128>>>(p_part, p_dinv, bb[s], p_hA);
        zdot_kernel<<<(n + 7) / 8, 256>>>(p_hA, Wp[s], p_z, n);
        baseSK_kernel<<<nb, 256>>>(p_z, p_dinv, bp[s], p_score, p_keys, n);
        hubfixSK_kernel<<<5, 256>>>(p_z, p_dinv, ecur, bp[s], p_score, p_keys, n);

        // multiblock bitonic sort
        int nblk = n / CHUNK;
        sort_local_kernel<<<nblk, 1024>>>(p_keys);
        for (int kk = 2 * CHUNK; kk <= n; kk <<= 1) {
            for (int j = kk >> 1; j >= CHUNK; j >>= 1)
                sort_cross_kernel<<<(n / 2 + 255) / 256, 256>>>(p_keys, n, kk, j);
            sort_finish_kernel<<<nblk, 1024>>>(p_keys, kk);
        }

        extract_kernel<<<nb, 256>>>(p_keys, p_score, p_idx, p_sv, p_newid, p_indeg, n, k);
        pool_kernel<<<k / 32, 128>>>(p_hA, xin, pin, ecur, p_idx, p_sv, p_newid,
                                     p_hB, p_xs[s & 1], p_perm[s & 1], enext,
                                     p_indeg, s);
    }

    mlp_kernel<<<1, 256>>>(L1w, L1b, L2w, L2b, L3w, L3b, out);
    outxp_kernel<<<(1024 * HDIM + 1024 + 255) / 256, 256>>>(p_xs[0], p_perm[0], out);
    a3_kernel<<<1024, 256>>>(p_edges[1], out + 40 + 1024 * HDIM + 1024);
}

// round 7
// speedup vs baseline: 1.6606x; 1.3000x over previous
#include <cuda_runtime.h>
#include <cstdint>

#define NMAX 8192
#define HDIM 128
#define RPB 32      // rows per gemm block
#define CHUNK 2048  // sort chunk per block
#define CHUNKS 64   // hub-partial chunks (R4-exact)

// ============================================================================
// Device scratch
// ============================================================================
__device__ int   g_edges[2][NMAX * 5];
__device__ float g_y[NMAX * HDIM];
__device__ float g_hA[NMAX * HDIM];
__device__ float g_hB[NMAX * HDIM];
__device__ float g_xs[2][NMAX * HDIM];
__device__ int   g_perm[2][NMAX];
__device__ int   g_indeg[NMAX];
__device__ float g_dinv[NMAX];
__device__ float g_z[NMAX];
__device__ float g_score[NMAX];
__device__ unsigned long long g_keys[NMAX];
__device__ int   g_idx[NMAX];
__device__ float g_sv[NMAX];
__device__ int   g_newid[NMAX];
__device__ int   g_hubs[5];
__device__ int   g_nhubs;
__device__ float g_part[CHUNKS * 5 * HDIM];
__device__ unsigned char g_mask[NMAX];
__device__ unsigned g_rmax[3][HDIM];
__device__ float g_rsum[3][HDIM];

// ============================================================================
// Helpers
// ============================================================================
__device__ __forceinline__ unsigned ordf(float v) {
    unsigned u = __float_as_uint(v);
    return (u & 0x80000000u) ? ~u : (u | 0x80000000u);
}
__device__ __forceinline__ float deco(unsigned e) {
    unsigned u = (e & 0x80000000u) ? (e & 0x7fffffffu) : ~e;
    return __uint_as_float(u);
}

// ============================================================================
// Init: degenerate stage-0 edges (eye*inf NaN semantics), closed-form indeg,
// zero readout accumulators.
// ============================================================================
__global__ void init_kernel(int* __restrict__ eout, int* __restrict__ indeg) {
    int i = blockIdx.x * 256 + threadIdx.x;
    if (i < NMAX) {
        int pos = 0;
        #pragma unroll
        for (int j = 0; j < 5; j++)
            if (j != i && pos < 4) eout[i * 5 + (pos++)] = j;
        eout[i * 5 + 4] = -1;
        indeg[i] = (i < 4) ? (NMAX - 1) : ((i == 4) ? 4 : 0);
    }
    if (i < 3 * HDIM) {
        (&g_rmax[0][0])[i] = 0u;
        (&g_rsum[0][0])[i] = 0.f;
    }
}

// ============================================================================
// dinv + hub detection (1 block) — dinv expression identical to R4
// ============================================================================
__global__ void dinvhubs_kernel(const int* __restrict__ indeg,
                                float* __restrict__ dinv, int n) {
    __shared__ int cnt;
    __shared__ int sl[16];
    int t = threadIdx.x;
    if (t == 0) cnt = 0;
    __syncthreads();
    for (int i = t; i < n; i += 1024) {
        int d = indeg[i];
        float deg = 1.f + (float)d;
        dinv[i] = 1.0f / sqrtf(deg);
        if (d > 0) {
            int p = atomicAdd(&cnt, 1);
            if (p < 16) sl[p] = i;
        }
    }
    __syncthreads();
    if (t == 0) {
        int m = cnt < 5 ? cnt : 5;
        for (int i = 1; i < m; i++) {
            int v = sl[i], j = i - 1;
            while (j >= 0 && sl[j] > v) { sl[j + 1] = sl[j]; j--; }
            sl[j + 1] = v;
        }
        g_nhubs = m;
        #pragma unroll
        for (int k = 0; k < 5; k++) g_hubs[k] = (k < m) ? sl[k] : -1;
    }
}

// ============================================================================
// Per-row hub mask: bit hk set iff row r touches hub hk (edge or self).
// Identical boolean to R4's inline computation.
// ============================================================================
__global__ void mask_kernel(const int* __restrict__ edges,
                            unsigned char* __restrict__ mask, int n) {
    __shared__ int shub[5];
    if (threadIdx.x < 5) shub[threadIdx.x] = g_hubs[threadIdx.x];
    __syncthreads();
    int r = blockIdx.x * 256 + threadIdx.x;
    if (r >= n) return;
    int e0 = edges[r * 5 + 0], e1 = edges[r * 5 + 1], e2 = edges[r * 5 + 2];
    int e3 = edges[r * 5 + 3], e4 = edges[r * 5 + 4];
    unsigned m = 0;
    #pragma unroll
    for (int k = 0; k < 5; k++) {
        int hv = shub[k];
        bool hit = (hv >= 0) &&
                   (e0 == hv || e1 == hv || e2 == hv || e3 == hv || e4 == hv || r == hv);
        if (hit) m |= 1u << k;
    }
    mask[r] = (unsigned char)m;
}

// ============================================================================
// Fused GEMM + base hA: y = h@W (32 rows/block, ascending-k fmaf chain ==
// R4 bits), y stored for hub pipeline, hA = relu(dinv^2*y + b) (R4 bits).
// ============================================================================
__global__ void gemmF_kernel(const float* __restrict__ h, const float* __restrict__ W,
                             const float* __restrict__ b, const float* __restrict__ dinv,
                             float* __restrict__ y, float* __restrict__ hA) {
    __shared__ float hs[RPB][HDIM];
    __shared__ float sdi[RPB];
    const int c = threadIdx.x;
    const int r0 = blockIdx.x * RPB;
    if (c < RPB) sdi[c] = dinv[r0 + c];
    #pragma unroll
    for (int r = 0; r < RPB; r++) hs[r][c] = h[(size_t)(r0 + r) * HDIM + c];
    __syncthreads();
    float acc[RPB];
    #pragma unroll
    for (int r = 0; r < RPB; r++) acc[r] = 0.f;
    #pragma unroll 4
    for (int k = 0; k < HDIM; k++) {
        float w = W[k * HDIM + c];
        #pragma unroll
        for (int r = 0; r < RPB; r++) acc[r] = fmaf(hs[r][k], w, acc[r]);
    }
    float bc = b[c];
    #pragma unroll
    for (int r = 0; r < RPB; r++) {
        y[(size_t)(r0 + r) * HDIM + c] = acc[r];
        float dc = sdi[r];
        float v = fmaf(dc * dc, acc[r], bc);
        hA[(size_t)(r0 + r) * HDIM + c] = fmaxf(v, 0.f);
    }
}

// ============================================================================
// Hub partials: 64 chunks, ascending rows, fadd chain (R4 bits).
// 8-wide batched loads (MLP=8) with mask table; chain order unchanged.
// ============================================================================
__global__ void hubpartF_kernel(const float* __restrict__ y, const float* __restrict__ dinv,
                                const unsigned char* __restrict__ mask,
                                float* __restrict__ part, int n) {
    int f = threadIdx.x;
    int ch = blockIdx.x;
    int rpc = n >> 6;   // 128/64/32, divisible by 8
    float acc[5] = {0.f, 0.f, 0.f, 0.f, 0.f};
    int rbeg = ch * rpc;
    for (int rb = rbeg; rb < rbeg + rpc; rb += 8) {
        float wv[8];
        unsigned mm[8];
        #pragma unroll
        for (int q = 0; q < 8; q++) {
            mm[q] = mask[rb + q];
            wv[q] = dinv[rb + q] * y[(size_t)(rb + q) * HDIM + f];
        }
        #pragma unroll
        for (int q = 0; q < 8; q++) {
            #pragma unroll
            for (int k = 0; k < 5; k++)
                if ((mm[q] >> k) & 1u) acc[k] += wv[q];
        }
    }
    #pragma unroll
    for (int k = 0; k < 5; k++) part[(ch * 5 + k) * HDIM + f] = acc[k];
}

// R4-verbatim: reduce chunks ascending, write hub hA rows
__global__ void hubfixF_kernel(const float* __restrict__ part, const float* __restrict__ dinv,
                               const float* __restrict__ b, float* __restrict__ out) {
    int k = blockIdx.x;
    if (k >= g_nhubs) return;
    int f = threadIdx.x;
    float S = 0.f;
    for (int ch = 0; ch < CHUNKS; ch++) S += part[(ch * 5 + k) * HDIM + f];
    int c = g_hubs[k];
    float v = fmaf(dinv[c], S, b[f]);
    out[(size_t)c * HDIM + f] = fmaxf(v, 0.f);
}

// ============================================================================
// z + base score + key (fused; score expression bit-identical to R4 baseS)
// ============================================================================
__global__ void zdotSK_kernel(const float* __restrict__ h, const float* __restrict__ Wp,
                              const float* __restrict__ dinv, const float* __restrict__ bp,
                              float* __restrict__ z, float* __restrict__ score,
                              unsigned long long* __restrict__ keys, int n) {
    int w = threadIdx.x >> 5, lane = threadIdx.x & 31;
    int r = blockIdx.x * 8 + w;
    if (r >= n) return;
    float s = 0.f;
    #pragma unroll
    for (int kk = lane; kk < HDIM; kk += 32)
        s = fmaf(h[(size_t)r * HDIM + kk], Wp[kk], s);
    #pragma unroll
    for (int o = 16; o > 0; o >>= 1) s += __shfl_down_sync(0xffffffffu, s, o);
    if (lane == 0) {
        z[r] = s;
        float dc = dinv[r];
        float sc = fmaf(dc * dc, s, bp[0]);
        score[r] = sc;
        keys[r] = ((unsigned long long)(~ordf(sc)) << 32) | (unsigned)r;
    }
}

// R4-verbatim hub score (256 threads, strided, tree) + key pack; mask table
__global__ void hubfixSK_kernel(const float* __restrict__ z, const float* __restrict__ dinv,
                                const unsigned char* __restrict__ mask,
                                const float* __restrict__ bp,
                                float* __restrict__ score,
                                unsigned long long* __restrict__ keys, int n) {
    int k = blockIdx.x;
    if (k >= g_nhubs) return;
    int hub = g_hubs[k];
    __shared__ float red[256];
    int t = threadIdx.x;
    float p = 0.f;
    for (int r = t; r < n; r += 256) {
        if ((mask[r] >> k) & 1u) p += dinv[r] * z[r];
    }
    red[t] = p;
    __syncthreads();
    for (int o = 128; o > 0; o >>= 1) {
        if (t < o) red[t] += red[t + o];
        __syncthreads();
    }
    if (t == 0) {
        float sc = fmaf(dinv[hub], red[0], bp[0]);
        score[hub] = sc;
        keys[hub] = ((unsigned long long)(~ordf(sc)) << 32) | (unsigned)hub;
    }
}

// ============================================================================
// Multi-block bitonic sort
// ============================================================================
__global__ void sort_local_kernel(unsigned long long* __restrict__ keys) {
    __shared__ unsigned long long sk[CHUNK];
    int t = threadIdx.x;
    int g0 = blockIdx.x * CHUNK;
    sk[t] = keys[g0 + t];
    sk[t + 1024] = keys[g0 + t + 1024];
    __syncthreads();
    for (int k = 2; k <= CHUNK; k <<= 1) {
        for (int j = k >> 1; j > 0; j >>= 1) {
            int i = ((t / j) * 2 * j) + (t % j);
            int ixj = i + j;
            bool up = (((g0 + i) & k) == 0);
            unsigned long long a = sk[i], bb = sk[ixj];
            if ((a > bb) == up) { sk[i] = bb; sk[ixj] = a; }
            __syncthreads();
        }
    }
    keys[g0 + t] = sk[t];
    keys[g0 + t + 1024] = sk[t + 1024];
}

__global__ void sort_cross_kernel(unsigned long long* __restrict__ keys,
                                  int n, int k, int j) {
    int t = blockIdx.x * 256 + threadIdx.x;
    if (t >= n / 2) return;
    int i = ((t / j) * 2 * j) + (t % j);
    int ixj = i + j;
    bool up = ((i & k) == 0);
    unsigned long long a = keys[i], bb = keys[ixj];
    if ((a > bb) == up) { keys[i] = bb; keys[ixj] = a; }
}

__global__ void sort_finish_kernel(unsigned long long* __restrict__ keys, int k) {
    __shared__ unsigned long long sk[CHUNK];
    int t = threadIdx.x;
    int g0 = blockIdx.x * CHUNK;
    sk[t] = keys[g0 + t];
    sk[t + 1024] = keys[g0 + t + 1024];
    __syncthreads();
    for (int j = 1024; j > 0; j >>= 1) {
        int i = ((t / j) * 2 * j) + (t % j);
        int ixj = i + j;
        bool up = (((g0 + i) & k) == 0);
        unsigned long long a = sk[i], bb = sk[ixj];
        if ((a > bb) == up) { sk[i] = bb; sk[ixj] = a; }
        __syncthreads();
    }
    keys[g0 + t] = sk[t];
    keys[g0 + t + 1024] = sk[t + 1024];
}

// ============================================================================
// Extract + newid + zero next indeg
// ============================================================================
__global__ void extract_kernel(const unsigned long long* __restrict__ keys,
                               const float* __restrict__ score,
                               int* __restrict__ idx, float* __restrict__ sv,
                               int* __restrict__ newid, int* __restrict__ indeg,
                               int n, int k) {
    int i = blockIdx.x * 256 + threadIdx.x;
    if (i >= n) return;
    int id = (int)(keys[i] & 0xffffffffull);
    newid[id] = (i < k) ? i : -1;
    if (i < k) {
        idx[i] = id;
        sv[i] = score[id];
        indeg[i] = 0;
    }
}

// ============================================================================
// Pool (32 new nodes/block): gather+gate h, gather xs/perm, remap edges,
// next indeg count, block-reduced readout atomics (set-invariant).
// ============================================================================
__global__ void pool_kernel(const float* __restrict__ h, const float* __restrict__ xs,
                            const int* __restrict__ perm, const int* __restrict__ edges,
                            const int* __restrict__ idx, const float* __restrict__ sv,
                            const int* __restrict__ newid,
                            float* __restrict__ h2, float* __restrict__ xs2,
                            int* __restrict__ perm2, int* __restrict__ edges2,
                            int* __restrict__ indeg, int stage) {
    __shared__ int sidx[32];
    __shared__ float sg[32];
    int c = threadIdx.x;
    int a0 = blockIdx.x * 32;
    if (c < 32) {
        sidx[c] = idx[a0 + c];
        sg[c] = tanhf(sv[a0 + c]);
    }
    __syncthreads();
    float lmax = -3.4e38f, lsum = 0.f;
    for (int rr = 0; rr < 32; rr++) {
        int a = a0 + rr;
        int o = sidx[rr];
        float v = h[(size_t)o * HDIM + c] * sg[rr];
        h2[(size_t)a * HDIM + c] = v;
        xs2[(size_t)a * HDIM + c] = xs[(size_t)o * HDIM + c];
        lmax = fmaxf(lmax, v);
        lsum += v;
        if (c < 5) {
            int e = edges[o * 5 + c];
            int ne = (e >= 0) ? newid[e] : -1;
            edges2[a * 5 + c] = ne;
            if (ne >= 0) atomicAdd(&indeg[ne], 1);
        }
        if (c == 5) perm2[a] = (perm != nullptr) ? perm[o] : o;
    }
    atomicMax(&g_rmax[stage][c], ordf(lmax));
    atomicAdd(&g_rsum[stage][c], lsum);
}

// ============================================================================
// Final MLP + log_softmax
// ============================================================================
__global__ void mlp_kernel(const float* __restrict__ L1w, const float* __restrict__ L1b,
                           const float* __restrict__ L2w, const float* __restrict__ L2b,
                           const float* __restrict__ L3w, const float* __restrict__ L3b,
                           float* __restrict__ out) {
    __shared__ float zin[256], z1[128], z2[64], z3[40];
    int t = threadIdx.x;
    if (t < 128) {
        zin[t] = deco(g_rmax[0][t]) + deco(g_rmax[1][t]) + deco(g_rmax[2][t]);
        zin[128 + t] = g_rsum[0][t] / 4096.f + g_rsum[1][t] / 2048.f + g_rsum[2][t] / 1024.f;
    }
    __syncthreads();
    if (t < 128) {
        float a = 0.f;
        for (int i = 0; i < 256; i++) a = fmaf(zin[i], L1w[i * 128 + t], a);
        z1[t] = fmaxf(a + L1b[t], 0.f);
    }
    __syncthreads();
    if (t < 64) {
        float a = 0.f;
        for (int i = 0; i < 128; i++) a = fmaf(z1[i], L2w[i * 64 + t], a);
        z2[t] = fmaxf(a + L2b[t], 0.f);
    }
    __syncthreads();
    if (t < 40) {
        float a = 0.f;
        for (int i = 0; i < 64; i++) a = fmaf(z2[i], L3w[i * 40 + t], a);
        z3[t] = a + L3b[t];
    }
    __syncthreads();
    if (t == 0) {
        float m = z3[0];
        for (int i = 1; i < 40; i++) m = fmaxf(m, z3[i]);
        float s = 0.f;
        for (int i = 0; i < 40; i++) s += expf(z3[i] - m);
        float l = m + logf(s);
        for (int i = 0; i < 40; i++) out[i] = z3[i] - l;
    }
}

__global__ void outxp_kernel(const float* __restrict__ xs, const int* __restrict__ perm,
                             float* __restrict__ out) {
    int i = blockIdx.x * 256 + threadIdx.x;
    if (i < 1024 * HDIM) out[40 + i] = xs[i];
    else if (i < 1024 * HDIM + 1024)
        out[40 + 1024 * HDIM + (i - 1024 * HDIM)] = (float)perm[i - 1024 * HDIM];
}

__global__ void a3_kernel(const int* __restrict__ edges, float* __restrict__ out) {
    int b = blockIdx.x;
    float* row = out + (size_t)b * 1024;
    for (int i = threadIdx.x; i < 1024; i += 256) row[i] = 0.f;
    __syncthreads();
    if (threadIdx.x == 0) {
        row[b] = 1.f;
        #pragma unroll
        for (int e = 0; e < 5; e++) {
            int tgt = edges[b * 5 + e];
            if (tgt >= 0) row[tgt] = 1.f;
        }
    }
}

// ============================================================================
// Host launcher
// ============================================================================
extern "C" void kernel_launch(void* const* d_in, const int* in_sizes, int n_in,
                              void* d_out, int out_size) {
    (void)in_sizes; (void)n_in; (void)out_size;
    const float* x0  = (const float*)d_in[0];
    const float* W[3]  = {(const float*)d_in[2], (const float*)d_in[4], (const float*)d_in[6]};
    const float* bb[3] = {(const float*)d_in[3], (const float*)d_in[5], (const float*)d_in[7]};
    const float* Wp[3] = {(const float*)d_in[8], (const float*)d_in[10], (const float*)d_in[12]};
    const float* bp[3] = {(const float*)d_in[9], (const float*)d_in[11], (const float*)d_in[13]};
    const float* L1w = (const float*)d_in[14];
    const float* L1b = (const float*)d_in[15];
    const float* L2w = (const float*)d_in[16];
    const float* L2b = (const float*)d_in[17];
    const float* L3w = (const float*)d_in[18];
    const float* L3b = (const float*)d_in[19];
    float* out = (float*)d_out;

    float *p_y, *p_hA, *p_hB, *p_dinv, *p_z, *p_score, *p_sv, *p_xsb, *p_part;
    int *p_edgesb, *p_indeg, *p_idx, *p_newid, *p_permb;
    unsigned char* p_mask;
    unsigned long long* p_keys;
    cudaGetSymbolAddress((void**)&p_edgesb, g_edges);
    cudaGetSymbolAddress((void**)&p_y, g_y);
    cudaGetSymbolAddress((void**)&p_hA, g_hA);
    cudaGetSymbolAddress((void**)&p_hB, g_hB);
    cudaGetSymbolAddress((void**)&p_xsb, g_xs);
    cudaGetSymbolAddress((void**)&p_permb, g_perm);
    cudaGetSymbolAddress((void**)&p_indeg, g_indeg);
    cudaGetSymbolAddress((void**)&p_dinv, g_dinv);
    cudaGetSymbolAddress((void**)&p_z, g_z);
    cudaGetSymbolAddress((void**)&p_score, g_score);
    cudaGetSymbolAddress((void**)&p_keys, g_keys);
    cudaGetSymbolAddress((void**)&p_idx, g_idx);
    cudaGetSymbolAddress((void**)&p_sv, g_sv);
    cudaGetSymbolAddress((void**)&p_newid, g_newid);
    cudaGetSymbolAddress((void**)&p_part, g_part);
    cudaGetSymbolAddress((void**)&p_mask, g_mask);

    int* p_edges[2] = {p_edgesb, p_edgesb + NMAX * 5};
    float* p_xs[2] = {p_xsb, p_xsb + (size_t)NMAX * HDIM};
    int* p_perm[2] = {p_permb, p_permb + NMAX};

    init_kernel<<<NMAX / 256, 256>>>(p_edges[0], p_indeg);

    for (int s = 0; s < 3; s++) {
        int n = NMAX >> s;
        int k = n >> 1;
        int nb = (n + 255) / 256;
        int* ecur = p_edges[s & 1];
        int* enext = p_edges[(s + 1) & 1];
        const float* hin = (s == 0) ? x0 : p_hB;
        const float* xin = (s == 0) ? x0 : p_xs[(s - 1) & 1];
        const int* pin = (s == 0) ? nullptr : p_perm[(s - 1) & 1];

        dinvhubs_kernel<<<1, 1024>>>(p_indeg, p_dinv, n);
        mask_kernel<<<nb, 256>>>(ecur, p_mask, n);

        // feature pipeline (score bits == R4)
        gemmF_kernel<<<n / RPB, 128>>>(hin, W[s], bb[s], p_dinv, p_y, p_hA);
        hubpartF_kernel<<<CHUNKS, 128>>>(p_y, p_dinv, p_mask, p_part, n);
        hubfixF_kernel<<<5, 128>>>(p_part, p_dinv, bb[s], p_hA);
        zdotSK_kernel<<<(n + 7) / 8, 256>>>(p_hA, Wp[s], p_dinv, bp[s],
                                            p_z, p_score, p_keys, n);
        hubfixSK_kernel<<<5, 256>>>(p_z, p_dinv, p_mask, bp[s], p_score, p_keys, n);

        // multiblock bitonic sort
        int nblk = n / CHUNK;
        sort_local_kernel<<<nblk, 1024>>>(p_keys);
        for (int kk = 2 * CHUNK; kk <= n; kk <<= 1) {
            for (int j = kk >> 1; j >= CHUNK; j >>= 1)
                sort_cross_kernel<<<(n / 2 + 255) / 256, 256>>>(p_keys, n, kk, j);
            sort_finish_kernel<<<nblk, 1024>>>(p_keys, kk);
        }

        extract_kernel<<<nb, 256>>>(p_keys, p_score, p_idx, p_sv, p_newid, p_indeg, n, k);
        pool_kernel<<<k / 32, 128>>>(p_hA, xin, pin, ecur, p_idx, p_sv, p_newid,
                                     p_hB, p_xs[s & 1], p_perm[s & 1], enext,
                                     p_indeg, s);
    }

    mlp_kernel<<<1, 256>>>(L1w, L1b, L2w, L2b, L3w, L3b, out);
    outxp_kernel<<<(1024 * HDIM + 1024 + 255) / 256, 256>>>(p_xs[0], p_perm[0], out);
    a3_kernel<<<1024, 256>>>(p_edges[1], out + 40 + 1024 * HDIM + 1024);
}